// round 3
// baseline (speedup 1.0000x reference)
#include <cuda_runtime.h>
#include <cstdint>
#include <cstddef>

#define TOKENS 8192
#define HDIM 1024
#define FFDIM 4096
#define NEXP 8
#define SLOTS (TOKENS*2)
#define RBLOCKS (TOKENS/8)

// ---------------- scratch (device globals; no allocation allowed) ----------------
__device__ float g_H[(size_t)SLOTS * FFDIM];   // 256 MB: silu(gate)*up per slot
__device__ float g_O[(size_t)SLOTS * HDIM];    // 64 MB: per-slot expert output
__device__ int   g_perm[SLOTS];                // slot -> token
__device__ int   g_slot_of[TOKENS*2];          // (token,k) -> slot
__device__ float g_score[TOKENS*2];            // normalized top-2 scores
__device__ int   g_eidx[TOKENS*2];             // (token,k) -> expert
__device__ int   g_counts[NEXP];
__device__ int   g_cursor[NEXP];
__device__ int   g_offsets[NEXP+1];
__device__ float g_zpart[RBLOCKS];
__device__ float g_ppart[RBLOCKS*NEXP];

// ---------------- helpers ----------------
__device__ __forceinline__ uint32_t f2tf(float f) {
    uint32_t r; asm("cvt.rna.tf32.f32 %0, %1;" : "=r"(r) : "f"(f)); return r;
}

__device__ __forceinline__ void mma_tf32(float c[4], const uint32_t a[4], const uint32_t b[2]) {
    asm volatile(
        "mma.sync.aligned.m16n8k8.row.col.f32.tf32.tf32.f32 "
        "{%0,%1,%2,%3}, {%4,%5,%6,%7}, {%8,%9}, {%0,%1,%2,%3};\n"
        : "+f"(c[0]), "+f"(c[1]), "+f"(c[2]), "+f"(c[3])
        : "r"(a[0]), "r"(a[1]), "r"(a[2]), "r"(a[3]), "r"(b[0]), "r"(b[1]));
}

// ---------------- setup kernels ----------------
__global__ void zero_kernel() {
    int i = threadIdx.x;
    if (i < NEXP) { g_counts[i] = 0; g_cursor[i] = 0; }
}

// one warp per token: logits, softmax, top-2, loss partials
__global__ void router_kernel(const float* __restrict__ x, const float* __restrict__ wr) {
    __shared__ float s_z[8];
    __shared__ float s_p[8][NEXP];
    int warp = threadIdx.x >> 5, lane = threadIdx.x & 31;
    int t = blockIdx.x * 8 + warp;
    const float* xr = x + (size_t)t * HDIM;
    float acc[NEXP];
#pragma unroll
    for (int e = 0; e < NEXP; e++) acc[e] = 0.f;
    for (int i = lane; i < HDIM; i += 32) {
        float xv = xr[i];
        const float4* w4 = reinterpret_cast<const float4*>(wr + (size_t)i * NEXP);
        float4 w0 = w4[0], w1 = w4[1];
        acc[0] += xv * w0.x; acc[1] += xv * w0.y; acc[2] += xv * w0.z; acc[3] += xv * w0.w;
        acc[4] += xv * w1.x; acc[5] += xv * w1.y; acc[6] += xv * w1.z; acc[7] += xv * w1.w;
    }
#pragma unroll
    for (int e = 0; e < NEXP; e++)
#pragma unroll
        for (int o = 16; o > 0; o >>= 1) acc[e] += __shfl_xor_sync(0xffffffffu, acc[e], o);

    if (lane == 0) {
        float z = 0.f, mx = acc[0];
#pragma unroll
        for (int e = 0; e < NEXP; e++) { z += acc[e] * acc[e]; mx = fmaxf(mx, acc[e]); }
        float p[NEXP], s = 0.f;
#pragma unroll
        for (int e = 0; e < NEXP; e++) { p[e] = expf(acc[e] - mx); s += p[e]; }
        float inv = 1.f / s;
#pragma unroll
        for (int e = 0; e < NEXP; e++) p[e] *= inv;
        int i0 = 0;
#pragma unroll
        for (int e = 1; e < NEXP; e++) if (p[e] > p[i0]) i0 = e;
        int i1 = (i0 == 0) ? 1 : 0;
#pragma unroll
        for (int e = 0; e < NEXP; e++) if (e != i0 && p[e] > p[i1]) i1 = e;
        float s0 = p[i0], s1 = p[i1], sn = 1.f / (s0 + s1);
        g_eidx[t*2] = i0;  g_eidx[t*2+1] = i1;
        g_score[t*2] = s0 * sn; g_score[t*2+1] = s1 * sn;
        atomicAdd(&g_counts[i0], 1); atomicAdd(&g_counts[i1], 1);
        s_z[warp] = z;
#pragma unroll
        for (int e = 0; e < NEXP; e++) s_p[warp][e] = p[e];
    }
    __syncthreads();
    if (threadIdx.x == 0) {
        float z = 0.f;
#pragma unroll
        for (int w = 0; w < 8; w++) z += s_z[w];
        g_zpart[blockIdx.x] = z;
    }
    if (threadIdx.x < NEXP) {
        float ps = 0.f;
#pragma unroll
        for (int w = 0; w < 8; w++) ps += s_p[w][threadIdx.x];
        g_ppart[blockIdx.x * NEXP + threadIdx.x] = ps;
    }
}

__global__ void scan_kernel() {
    if (threadIdx.x == 0) {
        int o = 0;
        for (int e = 0; e < NEXP; e++) { g_offsets[e] = o; o += g_counts[e]; }
        g_offsets[NEXP] = o;
    }
}

__global__ void scatter_kernel() {
    int t = blockIdx.x * blockDim.x + threadIdx.x;
    if (t >= TOKENS) return;
#pragma unroll
    for (int k = 0; k < 2; k++) {
        int e = g_eidx[t*2+k];
        int pos = atomicAdd(&g_cursor[e], 1);
        int slot = g_offsets[e] + pos;
        g_perm[slot] = t;
        g_slot_of[t*2+k] = slot;
    }
}

// ---------------- GEMM1: H[slot,:] = silu(X@Wg) * (X@Wu)  (fused, tf32) ----------------
// BM=128, BN=64 (per matrix), BK=32, 256 threads, warp grid 2(M)x4(N), warp tile 64x16
__global__ __launch_bounds__(256) void gemm1_kernel(const float* __restrict__ x,
                                                    const float* __restrict__ w_gate,
                                                    const float* __restrict__ w_up) {
    const int e = blockIdx.z;
    const int off = g_offsets[e];
    const int cnt = g_offsets[e+1] - off;
    const int m0 = blockIdx.y * 128;
    if (m0 >= cnt) return;
    const int n0 = blockIdx.x * 64;

    __shared__ __align__(16) uint32_t As[128*36];   // stride 36 (pad 4) -> conflict-free frags
    __shared__ __align__(16) uint32_t Bg[32*72];    // stride 72 (pad 8)
    __shared__ __align__(16) uint32_t Bu[32*72];

    const int tid = threadIdx.x, lane = tid & 31, wid = tid >> 5;
    const int wm = (wid & 1) * 64, wn = (wid >> 1) * 16;

    const int ac4 = tid & 7;            // A col/4 within BK (constant: 256 % 8 == 0)
    const float* aptr[4];
#pragma unroll
    for (int i = 0; i < 4; i++) {
        int r = (tid >> 3) + i * 32;
        int m = m0 + r;
        aptr[i] = (m < cnt) ? (x + (size_t)g_perm[off + m] * HDIM + ac4 * 4) : nullptr;
    }
    const int bc4 = tid & 15;
    const float* gptr[2]; const float* uptr[2];
#pragma unroll
    for (int i = 0; i < 2; i++) {
        int r = (tid >> 4) + i * 16;
        size_t o = (size_t)e * HDIM * FFDIM + (size_t)r * FFDIM + n0 + bc4 * 4;
        gptr[i] = w_gate + o; uptr[i] = w_up + o;
    }

    float cg[4][2][4], cu[4][2][4];
#pragma unroll
    for (int mi = 0; mi < 4; mi++)
#pragma unroll
        for (int ni = 0; ni < 2; ni++)
#pragma unroll
            for (int j = 0; j < 4; j++) { cg[mi][ni][j] = 0.f; cu[mi][ni][j] = 0.f; }

    for (int k0 = 0; k0 < HDIM; k0 += 32) {
#pragma unroll
        for (int i = 0; i < 4; i++) {
            uint4 v = {0u,0u,0u,0u};
            if (aptr[i]) {
                float4 f = *reinterpret_cast<const float4*>(aptr[i] + k0);
                v.x = f2tf(f.x); v.y = f2tf(f.y); v.z = f2tf(f.z); v.w = f2tf(f.w);
            }
            int r = (tid >> 3) + i * 32;
            *reinterpret_cast<uint4*>(&As[r*36 + ac4*4]) = v;
        }
#pragma unroll
        for (int i = 0; i < 2; i++) {
            int r = (tid >> 4) + i * 16;
            float4 fg = *reinterpret_cast<const float4*>(gptr[i] + (size_t)k0 * FFDIM);
            float4 fu = *reinterpret_cast<const float4*>(uptr[i] + (size_t)k0 * FFDIM);
            uint4 vg = { f2tf(fg.x), f2tf(fg.y), f2tf(fg.z), f2tf(fg.w) };
            uint4 vu = { f2tf(fu.x), f2tf(fu.y), f2tf(fu.z), f2tf(fu.w) };
            *reinterpret_cast<uint4*>(&Bg[r*72 + bc4*4]) = vg;
            *reinterpret_cast<uint4*>(&Bu[r*72 + bc4*4]) = vu;
        }
        __syncthreads();

#pragma unroll
        for (int kk = 0; kk < 4; kk++) {
            uint32_t a[4][4];
            const int fr = lane >> 2, fc = lane & 3;
#pragma unroll
            for (int mi = 0; mi < 4; mi++) {
                int rb = wm + mi * 16;
                a[mi][0] = As[(rb+fr  )*36 + kk*8 + fc    ];
                a[mi][1] = As[(rb+fr+8)*36 + kk*8 + fc    ];
                a[mi][2] = As[(rb+fr  )*36 + kk*8 + fc + 4];
                a[mi][3] = As[(rb+fr+8)*36 + kk*8 + fc + 4];
            }
            uint32_t bgf[2][2], buf[2][2];
            const int bk = lane & 3, bn = lane >> 2;
#pragma unroll
            for (int ni = 0; ni < 2; ni++) {
                int nb = wn + ni * 8;
                bgf[ni][0] = Bg[(kk*8+bk  )*72 + nb + bn];
                bgf[ni][1] = Bg[(kk*8+bk+4)*72 + nb + bn];
                buf[ni][0] = Bu[(kk*8+bk  )*72 + nb + bn];
                buf[ni][1] = Bu[(kk*8+bk+4)*72 + nb + bn];
            }
#pragma unroll
            for (int mi = 0; mi < 4; mi++)
#pragma unroll
                for (int ni = 0; ni < 2; ni++) {
                    mma_tf32(cg[mi][ni], a[mi], bgf[ni]);
                    mma_tf32(cu[mi][ni], a[mi], buf[ni]);
                }
        }
        __syncthreads();
    }

    const int fr = lane >> 2, fc2 = (lane & 3) * 2;
#pragma unroll
    for (int mi = 0; mi < 4; mi++) {
        int r1 = wm + mi * 16 + fr;
        int m1 = m0 + r1, m2 = m1 + 8;
#pragma unroll
        for (int ni = 0; ni < 2; ni++) {
            int col = n0 + wn + ni * 8 + fc2;
            if (m1 < cnt) {
                int slot = off + m1;
                float g0 = cg[mi][ni][0], g1 = cg[mi][ni][1];
                float u0 = cu[mi][ni][0], u1 = cu[mi][ni][1];
                float h0 = g0 / (1.f + expf(-g0)) * u0;
                float h1 = g1 / (1.f + expf(-g1)) * u1;
                *reinterpret_cast<float2*>(&g_H[(size_t)slot * FFDIM + col]) = make_float2(h0, h1);
            }
            if (m2 < cnt) {
                int slot = off + m2;
                float g0 = cg[mi][ni][2], g1 = cg[mi][ni][3];
                float u0 = cu[mi][ni][2], u1 = cu[mi][ni][3];
                float h0 = g0 / (1.f + expf(-g0)) * u0;
                float h1 = g1 / (1.f + expf(-g1)) * u1;
                *reinterpret_cast<float2*>(&g_H[(size_t)slot * FFDIM + col]) = make_float2(h0, h1);
            }
        }
    }
}

// ---------------- GEMM2: O[slot,:] = H[slot,:] @ Wd[e]  (tf32) ----------------
// BM=128, BN=128, BK=32, 256 threads, warp grid 2(M)x4(N), warp tile 64x32
__global__ __launch_bounds__(256) void gemm2_kernel(const float* __restrict__ w_down) {
    const int e = blockIdx.z;
    const int off = g_offsets[e];
    const int cnt = g_offsets[e+1] - off;
    const int m0 = blockIdx.y * 128;
    if (m0 >= cnt) return;
    const int n0 = blockIdx.x * 128;

    __shared__ __align__(16) uint32_t As[128*36];
    __shared__ __align__(16) uint32_t Bs[32*136];   // stride 136 (pad 8)

    const int tid = threadIdx.x, lane = tid & 31, wid = tid >> 5;
    const int wm = (wid & 1) * 64, wn = (wid >> 1) * 32;

    const int ac4 = tid & 7;
    const float* aptr[4];
#pragma unroll
    for (int i = 0; i < 4; i++) {
        int r = (tid >> 3) + i * 32;
        int m = m0 + r;
        aptr[i] = (m < cnt) ? (g_H + (size_t)(off + m) * FFDIM + ac4 * 4) : nullptr;
    }
    const int bc4 = tid & 31;
    const float* bptr[4];
#pragma unroll
    for (int i = 0; i < 4; i++) {
        int r = (tid >> 5) + i * 8;
        bptr[i] = w_down + (size_t)e * FFDIM * HDIM + (size_t)r * HDIM + n0 + bc4 * 4;
    }

    float c[4][4][4];
#pragma unroll
    for (int mi = 0; mi < 4; mi++)
#pragma unroll
        for (int ni = 0; ni < 4; ni++)
#pragma unroll
            for (int j = 0; j < 4; j++) c[mi][ni][j] = 0.f;

    for (int k0 = 0; k0 < FFDIM; k0 += 32) {
#pragma unroll
        for (int i = 0; i < 4; i++) {
            uint4 v = {0u,0u,0u,0u};
            if (aptr[i]) {
                float4 f = *reinterpret_cast<const float4*>(aptr[i] + k0);
                v.x = f2tf(f.x); v.y = f2tf(f.y); v.z = f2tf(f.z); v.w = f2tf(f.w);
            }
            int r = (tid >> 3) + i * 32;
            *reinterpret_cast<uint4*>(&As[r*36 + ac4*4]) = v;
        }
#pragma unroll
        for (int i = 0; i < 4; i++) {
            float4 f = *reinterpret_cast<const float4*>(bptr[i] + (size_t)k0 * HDIM);
            uint4 v = { f2tf(f.x), f2tf(f.y), f2tf(f.z), f2tf(f.w) };
            int r = (tid >> 5) + i * 8;
            *reinterpret_cast<uint4*>(&Bs[r*136 + bc4*4]) = v;
        }
        __syncthreads();

#pragma unroll
        for (int kk = 0; kk < 4; kk++) {
            uint32_t a[4][4];
            const int fr = lane >> 2, fc = lane & 3;
#pragma unroll
            for (int mi = 0; mi < 4; mi++) {
                int rb = wm + mi * 16;
                a[mi][0] = As[(rb+fr  )*36 + kk*8 + fc    ];
                a[mi][1] = As[(rb+fr+8)*36 + kk*8 + fc    ];
                a[mi][2] = As[(rb+fr  )*36 + kk*8 + fc + 4];
                a[mi][3] = As[(rb+fr+8)*36 + kk*8 + fc + 4];
            }
            uint32_t b[4][2];
            const int bk = lane & 3, bn = lane >> 2;
#pragma unroll
            for (int ni = 0; ni < 4; ni++) {
                int nb = wn + ni * 8;
                b[ni][0] = Bs[(kk*8+bk  )*136 + nb + bn];
                b[ni][1] = Bs[(kk*8+bk+4)*136 + nb + bn];
            }
#pragma unroll
            for (int mi = 0; mi < 4; mi++)
#pragma unroll
                for (int ni = 0; ni < 4; ni++)
                    mma_tf32(c[mi][ni], a[mi], b[ni]);
        }
        __syncthreads();
    }

    const int fr = lane >> 2, fc2 = (lane & 3) * 2;
#pragma unroll
    for (int mi = 0; mi < 4; mi++) {
        int r1 = wm + mi * 16 + fr;
        int m1 = m0 + r1, m2 = m1 + 8;
#pragma unroll
        for (int ni = 0; ni < 4; ni++) {
            int col = n0 + wn + ni * 8 + fc2;
            if (m1 < cnt)
                *reinterpret_cast<float2*>(&g_O[(size_t)(off+m1) * HDIM + col]) =
                    make_float2(c[mi][ni][0], c[mi][ni][1]);
            if (m2 < cnt)
                *reinterpret_cast<float2*>(&g_O[(size_t)(off+m2) * HDIM + col]) =
                    make_float2(c[mi][ni][2], c[mi][ni][3]);
        }
    }
}

// ---------------- combine + losses ----------------
__global__ void combine_kernel(float* __restrict__ out) {
    int idx = blockIdx.x * blockDim.x + threadIdx.x;   // TOKENS * 256 float4s
    int t = idx >> 8;
    int c4 = idx & 255;
    if (t >= TOKENS) return;
    int s0 = g_slot_of[t*2], s1 = g_slot_of[t*2+1];
    float w0 = g_score[t*2], w1 = g_score[t*2+1];
    float4 a = *reinterpret_cast<const float4*>(&g_O[(size_t)s0 * HDIM + c4*4]);
    float4 b = *reinterpret_cast<const float4*>(&g_O[(size_t)s1 * HDIM + c4*4]);
    float4 o;
    o.x = w0*a.x + w1*b.x; o.y = w0*a.y + w1*b.y;
    o.z = w0*a.z + w1*b.z; o.w = w0*a.w + w1*b.w;
    *reinterpret_cast<float4*>(&out[(size_t)t * HDIM + c4*4]) = o;
}

__global__ void loss_kernel(float* __restrict__ out) {
    int lane = threadIdx.x;   // 32 threads
    float z = 0.f, pe[NEXP];
#pragma unroll
    for (int e = 0; e < NEXP; e++) pe[e] = 0.f;
    for (int i = lane; i < RBLOCKS; i += 32) {
        z += g_zpart[i];
#pragma unroll
        for (int e = 0; e < NEXP; e++) pe[e] += g_ppart[i*NEXP + e];
    }
#pragma unroll
    for (int o = 16; o > 0; o >>= 1) {
        z += __shfl_xor_sync(0xffffffffu, z, o);
#pragma unroll
        for (int e = 0; e < NEXP; e++) pe[e] += __shfl_xor_sync(0xffffffffu, pe[e], o);
    }
    if (lane == 0) {
        float zl = (float)NEXP * (z / (float)((size_t)TOKENS * NEXP));
        float aux = 0.f;
#pragma unroll
        for (int e = 0; e < NEXP; e++) {
            float pm = pe[e] / (float)TOKENS;
            aux += pm * logf(pm + 1e-9f);
        }
        out[(size_t)TOKENS * HDIM    ] = zl;
        out[(size_t)TOKENS * HDIM + 1] = (float)NEXP * aux;
    }
}

// ---------------- launch ----------------
extern "C" void kernel_launch(void* const* d_in, const int* in_sizes, int n_in,
                              void* d_out, int out_size) {
    const float* x        = (const float*)d_in[0];
    const float* w_router = (const float*)d_in[1];
    const float* w_gate   = (const float*)d_in[2];
    const float* w_up     = (const float*)d_in[3];
    const float* w_down   = (const float*)d_in[4];
    float* out = (float*)d_out;

    zero_kernel<<<1, 32>>>();
    router_kernel<<<RBLOCKS, 256>>>(x, w_router);
    scan_kernel<<<1, 32>>>();
    scatter_kernel<<<TOKENS/256, 256>>>();
    // max tokens per expert = TOKENS (top-2 indices distinct) -> 64 M-tiles of 128
    gemm1_kernel<<<dim3(FFDIM/64, 64, NEXP), 256>>>(x, w_gate, w_up);
    gemm2_kernel<<<dim3(HDIM/128, 64, NEXP), 256>>>(w_down);
    combine_kernel<<<(TOKENS*256)/256, 256>>>(out);
    loss_kernel<<<1, 32>>>(out);
}

// round 4
// speedup vs baseline: 1.3559x; 1.3559x over previous
#include <cuda_runtime.h>
#include <cstdint>
#include <cstddef>

#define TOKENS 8192
#define HDIM 1024
#define FFDIM 4096
#define NEXP 8
#define SLOTS (TOKENS*2)
#define RBLOCKS (TOKENS/8)

// ---------------- scratch (device globals; no allocation allowed) ----------------
__device__ float g_H[(size_t)SLOTS * FFDIM];   // 256 MB: silu(gate)*up per slot
__device__ float g_O[(size_t)SLOTS * HDIM];    // 64 MB: per-slot expert output
__device__ int   g_perm[SLOTS];                // slot -> token
__device__ int   g_slot_of[TOKENS*2];          // (token,k) -> slot
__device__ float g_score[TOKENS*2];            // normalized top-2 scores
__device__ int   g_eidx[TOKENS*2];             // (token,k) -> expert
__device__ int   g_counts[NEXP];
__device__ int   g_cursor[NEXP];
__device__ int   g_offsets[NEXP+1];
__device__ float g_zpart[RBLOCKS];
__device__ float g_ppart[RBLOCKS*NEXP];

// ---------------- helpers ----------------
__device__ __forceinline__ uint32_t f2tf(float f) {
    uint32_t r; asm("cvt.rna.tf32.f32 %0, %1;" : "=r"(r) : "f"(f)); return r;
}
__device__ __forceinline__ uint32_t tf_of(uint32_t raw) {
    return f2tf(__uint_as_float(raw));
}

__device__ __forceinline__ void mma_tf32(float c[4], const uint32_t a[4], const uint32_t b[2]) {
    asm volatile(
        "mma.sync.aligned.m16n8k8.row.col.f32.tf32.tf32.f32 "
        "{%0,%1,%2,%3}, {%4,%5,%6,%7}, {%8,%9}, {%0,%1,%2,%3};\n"
        : "+f"(c[0]), "+f"(c[1]), "+f"(c[2]), "+f"(c[3])
        : "r"(a[0]), "r"(a[1]), "r"(a[2]), "r"(a[3]), "r"(b[0]), "r"(b[1]));
}

// cp.async 16B, zero-fill when srcbytes==0
__device__ __forceinline__ void cpa16(uint32_t saddr, const void* gsrc, int srcbytes) {
    asm volatile("cp.async.cg.shared.global [%0], [%1], 16, %2;\n"
                 :: "r"(saddr), "l"(gsrc), "r"(srcbytes));
}
__device__ __forceinline__ void cpa_commit() {
    asm volatile("cp.async.commit_group;\n" ::: "memory");
}
template <int N>
__device__ __forceinline__ void cpa_wait() {
    asm volatile("cp.async.wait_group %0;\n" :: "n"(N) : "memory");
}
__device__ __forceinline__ uint32_t smem_u32(const void* p) {
    return (uint32_t)__cvta_generic_to_shared(p);
}

// ---------------- setup kernels ----------------
__global__ void zero_kernel() {
    int i = threadIdx.x;
    if (i < NEXP) { g_counts[i] = 0; g_cursor[i] = 0; }
}

// one warp per token: logits, softmax, top-2, loss partials
__global__ void router_kernel(const float* __restrict__ x, const float* __restrict__ wr) {
    __shared__ float s_z[8];
    __shared__ float s_p[8][NEXP];
    int warp = threadIdx.x >> 5, lane = threadIdx.x & 31;
    int t = blockIdx.x * 8 + warp;
    const float* xr = x + (size_t)t * HDIM;
    float acc[NEXP];
#pragma unroll
    for (int e = 0; e < NEXP; e++) acc[e] = 0.f;
    for (int i = lane; i < HDIM; i += 32) {
        float xv = xr[i];
        const float4* w4 = reinterpret_cast<const float4*>(wr + (size_t)i * NEXP);
        float4 w0 = w4[0], w1 = w4[1];
        acc[0] += xv * w0.x; acc[1] += xv * w0.y; acc[2] += xv * w0.z; acc[3] += xv * w0.w;
        acc[4] += xv * w1.x; acc[5] += xv * w1.y; acc[6] += xv * w1.z; acc[7] += xv * w1.w;
    }
#pragma unroll
    for (int e = 0; e < NEXP; e++)
#pragma unroll
        for (int o = 16; o > 0; o >>= 1) acc[e] += __shfl_xor_sync(0xffffffffu, acc[e], o);

    if (lane == 0) {
        float z = 0.f, mx = acc[0];
#pragma unroll
        for (int e = 0; e < NEXP; e++) { z += acc[e] * acc[e]; mx = fmaxf(mx, acc[e]); }
        float p[NEXP], s = 0.f;
#pragma unroll
        for (int e = 0; e < NEXP; e++) { p[e] = expf(acc[e] - mx); s += p[e]; }
        float inv = 1.f / s;
#pragma unroll
        for (int e = 0; e < NEXP; e++) p[e] *= inv;
        int i0 = 0;
#pragma unroll
        for (int e = 1; e < NEXP; e++) if (p[e] > p[i0]) i0 = e;
        int i1 = (i0 == 0) ? 1 : 0;
#pragma unroll
        for (int e = 0; e < NEXP; e++) if (e != i0 && p[e] > p[i1]) i1 = e;
        float s0 = p[i0], s1 = p[i1], sn = 1.f / (s0 + s1);
        g_eidx[t*2] = i0;  g_eidx[t*2+1] = i1;
        g_score[t*2] = s0 * sn; g_score[t*2+1] = s1 * sn;
        atomicAdd(&g_counts[i0], 1); atomicAdd(&g_counts[i1], 1);
        s_z[warp] = z;
#pragma unroll
        for (int e = 0; e < NEXP; e++) s_p[warp][e] = p[e];
    }
    __syncthreads();
    if (threadIdx.x == 0) {
        float z = 0.f;
#pragma unroll
        for (int w = 0; w < 8; w++) z += s_z[w];
        g_zpart[blockIdx.x] = z;
    }
    if (threadIdx.x < NEXP) {
        float ps = 0.f;
#pragma unroll
        for (int w = 0; w < 8; w++) ps += s_p[w][threadIdx.x];
        g_ppart[blockIdx.x * NEXP + threadIdx.x] = ps;
    }
}

__global__ void scan_kernel() {
    if (threadIdx.x == 0) {
        int o = 0;
        for (int e = 0; e < NEXP; e++) { g_offsets[e] = o; o += g_counts[e]; }
        g_offsets[NEXP] = o;
    }
}

__global__ void scatter_kernel() {
    int t = blockIdx.x * blockDim.x + threadIdx.x;
    if (t >= TOKENS) return;
#pragma unroll
    for (int k = 0; k < 2; k++) {
        int e = g_eidx[t*2+k];
        int pos = atomicAdd(&g_cursor[e], 1);
        int slot = g_offsets[e] + pos;
        g_perm[slot] = t;
        g_slot_of[t*2+k] = slot;
    }
}

// ---------------- GEMM1: H[slot,:] = silu(X@Wg) * (X@Wu)  (fused, tf32, cp.async x2) ---
// BM=128, BN=64 (per matrix), BK=32, 256 threads, warp grid 2(M)x4(N)
// dyn smem: As 2*128*36 u32 + Bg 2*32*72 + Bu 2*32*72 = 73728 bytes
#define G1_AS (128*36)
#define G1_BS (32*72)
__global__ __launch_bounds__(256) void gemm1_kernel(const float* __restrict__ x,
                                                    const float* __restrict__ w_gate,
                                                    const float* __restrict__ w_up) {
    const int e = blockIdx.z;
    const int off = g_offsets[e];
    const int cnt = g_offsets[e+1] - off;
    const int m0 = blockIdx.y * 128;
    if (m0 >= cnt) return;
    const int n0 = blockIdx.x * 64;

    extern __shared__ uint32_t smem[];
    uint32_t* As = smem;                    // 2 * G1_AS
    uint32_t* Bg = smem + 2*G1_AS;          // 2 * G1_BS
    uint32_t* Bu = Bg + 2*G1_BS;            // 2 * G1_BS

    const int tid = threadIdx.x, lane = tid & 31, wid = tid >> 5;
    const int wm = (wid & 1) * 64, wn = (wid >> 1) * 16;

    const int ac4 = tid & 7;
    const float* aptr[4]; int avalid[4];
#pragma unroll
    for (int i = 0; i < 4; i++) {
        int r = (tid >> 3) + i * 32;
        int m = m0 + r;
        avalid[i] = (m < cnt) ? 16 : 0;
        aptr[i] = (m < cnt) ? (x + (size_t)g_perm[off + m] * HDIM + ac4 * 4) : x;
    }
    const int bc4 = tid & 15;
    const float* gptr[2]; const float* uptr[2];
#pragma unroll
    for (int i = 0; i < 2; i++) {
        int r = (tid >> 4) + i * 16;
        size_t o = (size_t)e * HDIM * FFDIM + (size_t)r * FFDIM + n0 + bc4 * 4;
        gptr[i] = w_gate + o; uptr[i] = w_up + o;
    }

    // precompute smem dst addrs (byte) for the two stages
    uint32_t a_dst[4], g_dst[2], u_dst[2];
#pragma unroll
    for (int i = 0; i < 4; i++) {
        int r = (tid >> 3) + i * 32;
        a_dst[i] = smem_u32(&As[r*36 + ac4*4]);
    }
#pragma unroll
    for (int i = 0; i < 2; i++) {
        int r = (tid >> 4) + i * 16;
        g_dst[i] = smem_u32(&Bg[r*72 + bc4*4]);
        u_dst[i] = smem_u32(&Bu[r*72 + bc4*4]);
    }

    float cg[4][2][4], cu[4][2][4];
#pragma unroll
    for (int mi = 0; mi < 4; mi++)
#pragma unroll
        for (int ni = 0; ni < 2; ni++)
#pragma unroll
            for (int j = 0; j < 4; j++) { cg[mi][ni][j] = 0.f; cu[mi][ni][j] = 0.f; }

    const int NSTEP = HDIM / 32;

    // prologue: stage 0
#pragma unroll
    for (int i = 0; i < 4; i++) cpa16(a_dst[i], aptr[i], avalid[i]);
#pragma unroll
    for (int i = 0; i < 2; i++) {
        cpa16(g_dst[i], gptr[i], 16);
        cpa16(u_dst[i], uptr[i], 16);
    }
    cpa_commit();

    for (int s = 0; s < NSTEP; s++) {
        const int cur = s & 1;
        if (s + 1 < NSTEP) {
            const int nxt = (s + 1) & 1;
            const int k0 = (s + 1) * 32;
            const uint32_t ao = nxt * G1_AS * 4, bo = nxt * G1_BS * 4;
#pragma unroll
            for (int i = 0; i < 4; i++) cpa16(a_dst[i] + ao, aptr[i] + k0, avalid[i]);
#pragma unroll
            for (int i = 0; i < 2; i++) {
                cpa16(g_dst[i] + bo, gptr[i] + (size_t)k0 * FFDIM, 16);
                cpa16(u_dst[i] + bo, uptr[i] + (size_t)k0 * FFDIM, 16);
            }
            cpa_commit();
            cpa_wait<1>();
        } else {
            cpa_wait<0>();
        }
        __syncthreads();

        const uint32_t* A = As + cur * G1_AS;
        const uint32_t* BG = Bg + cur * G1_BS;
        const uint32_t* BU = Bu + cur * G1_BS;

#pragma unroll
        for (int kk = 0; kk < 4; kk++) {
            uint32_t a[4][4];
            const int fr = lane >> 2, fc = lane & 3;
#pragma unroll
            for (int mi = 0; mi < 4; mi++) {
                int rb = wm + mi * 16;
                a[mi][0] = tf_of(A[(rb+fr  )*36 + kk*8 + fc    ]);
                a[mi][1] = tf_of(A[(rb+fr+8)*36 + kk*8 + fc    ]);
                a[mi][2] = tf_of(A[(rb+fr  )*36 + kk*8 + fc + 4]);
                a[mi][3] = tf_of(A[(rb+fr+8)*36 + kk*8 + fc + 4]);
            }
            uint32_t bgf[2][2], buf[2][2];
            const int bk = lane & 3, bn = lane >> 2;
#pragma unroll
            for (int ni = 0; ni < 2; ni++) {
                int nb = wn + ni * 8;
                bgf[ni][0] = tf_of(BG[(kk*8+bk  )*72 + nb + bn]);
                bgf[ni][1] = tf_of(BG[(kk*8+bk+4)*72 + nb + bn]);
                buf[ni][0] = tf_of(BU[(kk*8+bk  )*72 + nb + bn]);
                buf[ni][1] = tf_of(BU[(kk*8+bk+4)*72 + nb + bn]);
            }
#pragma unroll
            for (int mi = 0; mi < 4; mi++)
#pragma unroll
                for (int ni = 0; ni < 2; ni++) {
                    mma_tf32(cg[mi][ni], a[mi], bgf[ni]);
                    mma_tf32(cu[mi][ni], a[mi], buf[ni]);
                }
        }
        __syncthreads();
    }

    const int fr = lane >> 2, fc2 = (lane & 3) * 2;
#pragma unroll
    for (int mi = 0; mi < 4; mi++) {
        int r1 = wm + mi * 16 + fr;
        int m1 = m0 + r1, m2 = m1 + 8;
#pragma unroll
        for (int ni = 0; ni < 2; ni++) {
            int col = n0 + wn + ni * 8 + fc2;
            if (m1 < cnt) {
                int slot = off + m1;
                float g0 = cg[mi][ni][0], g1 = cg[mi][ni][1];
                float u0 = cu[mi][ni][0], u1 = cu[mi][ni][1];
                float h0 = g0 / (1.f + expf(-g0)) * u0;
                float h1 = g1 / (1.f + expf(-g1)) * u1;
                *reinterpret_cast<float2*>(&g_H[(size_t)slot * FFDIM + col]) = make_float2(h0, h1);
            }
            if (m2 < cnt) {
                int slot = off + m2;
                float g0 = cg[mi][ni][2], g1 = cg[mi][ni][3];
                float u0 = cu[mi][ni][2], u1 = cu[mi][ni][3];
                float h0 = g0 / (1.f + expf(-g0)) * u0;
                float h1 = g1 / (1.f + expf(-g1)) * u1;
                *reinterpret_cast<float2*>(&g_H[(size_t)slot * FFDIM + col]) = make_float2(h0, h1);
            }
        }
    }
}

// ---------------- GEMM2: O[slot,:] = H[slot,:] @ Wd[e]  (tf32, cp.async x2) -------------
// BM=128, BN=128, BK=32, 256 threads, warp grid 2(M)x4(N)
// dyn smem: As 2*128*36 + Bs 2*32*136 = 71680 bytes
#define G2_AS (128*36)
#define G2_BS (32*136)
__global__ __launch_bounds__(256) void gemm2_kernel(const float* __restrict__ w_down) {
    const int e = blockIdx.z;
    const int off = g_offsets[e];
    const int cnt = g_offsets[e+1] - off;
    const int m0 = blockIdx.y * 128;
    if (m0 >= cnt) return;
    const int n0 = blockIdx.x * 128;

    extern __shared__ uint32_t smem[];
    uint32_t* As = smem;             // 2 * G2_AS
    uint32_t* Bs = smem + 2*G2_AS;   // 2 * G2_BS

    const int tid = threadIdx.x, lane = tid & 31, wid = tid >> 5;
    const int wm = (wid & 1) * 64, wn = (wid >> 1) * 32;

    const int ac4 = tid & 7;
    const float* aptr[4]; int avalid[4];
#pragma unroll
    for (int i = 0; i < 4; i++) {
        int r = (tid >> 3) + i * 32;
        int m = m0 + r;
        avalid[i] = (m < cnt) ? 16 : 0;
        aptr[i] = (m < cnt) ? (g_H + (size_t)(off + m) * FFDIM + ac4 * 4) : g_H;
    }
    const int bc4 = tid & 31;
    const float* bptr[4];
#pragma unroll
    for (int i = 0; i < 4; i++) {
        int r = (tid >> 5) + i * 8;
        bptr[i] = w_down + (size_t)e * FFDIM * HDIM + (size_t)r * HDIM + n0 + bc4 * 4;
    }

    uint32_t a_dst[4], b_dst[4];
#pragma unroll
    for (int i = 0; i < 4; i++) {
        int r = (tid >> 3) + i * 32;
        a_dst[i] = smem_u32(&As[r*36 + ac4*4]);
    }
#pragma unroll
    for (int i = 0; i < 4; i++) {
        int r = (tid >> 5) + i * 8;
        b_dst[i] = smem_u32(&Bs[r*136 + bc4*4]);
    }

    float c[4][4][4];
#pragma unroll
    for (int mi = 0; mi < 4; mi++)
#pragma unroll
        for (int ni = 0; ni < 4; ni++)
#pragma unroll
            for (int j = 0; j < 4; j++) c[mi][ni][j] = 0.f;

    const int NSTEP = FFDIM / 32;

#pragma unroll
    for (int i = 0; i < 4; i++) cpa16(a_dst[i], aptr[i], avalid[i]);
#pragma unroll
    for (int i = 0; i < 4; i++) cpa16(b_dst[i], bptr[i], 16);
    cpa_commit();

    for (int s = 0; s < NSTEP; s++) {
        const int cur = s & 1;
        if (s + 1 < NSTEP) {
            const int nxt = (s + 1) & 1;
            const int k0 = (s + 1) * 32;
            const uint32_t ao = nxt * G2_AS * 4, bo = nxt * G2_BS * 4;
#pragma unroll
            for (int i = 0; i < 4; i++) cpa16(a_dst[i] + ao, aptr[i] + k0, avalid[i]);
#pragma unroll
            for (int i = 0; i < 4; i++) cpa16(b_dst[i] + bo, bptr[i] + (size_t)k0 * HDIM, 16);
            cpa_commit();
            cpa_wait<1>();
        } else {
            cpa_wait<0>();
        }
        __syncthreads();

        const uint32_t* A = As + cur * G2_AS;
        const uint32_t* B = Bs + cur * G2_BS;

#pragma unroll
        for (int kk = 0; kk < 4; kk++) {
            uint32_t a[4][4];
            const int fr = lane >> 2, fc = lane & 3;
#pragma unroll
            for (int mi = 0; mi < 4; mi++) {
                int rb = wm + mi * 16;
                a[mi][0] = tf_of(A[(rb+fr  )*36 + kk*8 + fc    ]);
                a[mi][1] = tf_of(A[(rb+fr+8)*36 + kk*8 + fc    ]);
                a[mi][2] = tf_of(A[(rb+fr  )*36 + kk*8 + fc + 4]);
                a[mi][3] = tf_of(A[(rb+fr+8)*36 + kk*8 + fc + 4]);
            }
            uint32_t b[4][2];
            const int bk = lane & 3, bn = lane >> 2;
#pragma unroll
            for (int ni = 0; ni < 4; ni++) {
                int nb = wn + ni * 8;
                b[ni][0] = tf_of(B[(kk*8+bk  )*136 + nb + bn]);
                b[ni][1] = tf_of(B[(kk*8+bk+4)*136 + nb + bn]);
            }
#pragma unroll
            for (int mi = 0; mi < 4; mi++)
#pragma unroll
                for (int ni = 0; ni < 4; ni++)
                    mma_tf32(c[mi][ni], a[mi], b[ni]);
        }
        __syncthreads();
    }

    const int fr = lane >> 2, fc2 = (lane & 3) * 2;
#pragma unroll
    for (int mi = 0; mi < 4; mi++) {
        int r1 = wm + mi * 16 + fr;
        int m1 = m0 + r1, m2 = m1 + 8;
#pragma unroll
        for (int ni = 0; ni < 4; ni++) {
            int col = n0 + wn + ni * 8 + fc2;
            if (m1 < cnt)
                *reinterpret_cast<float2*>(&g_O[(size_t)(off+m1) * HDIM + col]) =
                    make_float2(c[mi][ni][0], c[mi][ni][1]);
            if (m2 < cnt)
                *reinterpret_cast<float2*>(&g_O[(size_t)(off+m2) * HDIM + col]) =
                    make_float2(c[mi][ni][2], c[mi][ni][3]);
        }
    }
}

// ---------------- combine + losses ----------------
__global__ void combine_kernel(float* __restrict__ out) {
    int idx = blockIdx.x * blockDim.x + threadIdx.x;   // TOKENS * 256 float4s
    int t = idx >> 8;
    int c4 = idx & 255;
    if (t >= TOKENS) return;
    int s0 = g_slot_of[t*2], s1 = g_slot_of[t*2+1];
    float w0 = g_score[t*2], w1 = g_score[t*2+1];
    float4 a = *reinterpret_cast<const float4*>(&g_O[(size_t)s0 * HDIM + c4*4]);
    float4 b = *reinterpret_cast<const float4*>(&g_O[(size_t)s1 * HDIM + c4*4]);
    float4 o;
    o.x = w0*a.x + w1*b.x; o.y = w0*a.y + w1*b.y;
    o.z = w0*a.z + w1*b.z; o.w = w0*a.w + w1*b.w;
    *reinterpret_cast<float4*>(&out[(size_t)t * HDIM + c4*4]) = o;
}

__global__ void loss_kernel(float* __restrict__ out) {
    int lane = threadIdx.x;   // 32 threads
    float z = 0.f, pe[NEXP];
#pragma unroll
    for (int e = 0; e < NEXP; e++) pe[e] = 0.f;
    for (int i = lane; i < RBLOCKS; i += 32) {
        z += g_zpart[i];
#pragma unroll
        for (int e = 0; e < NEXP; e++) pe[e] += g_ppart[i*NEXP + e];
    }
#pragma unroll
    for (int o = 16; o > 0; o >>= 1) {
        z += __shfl_xor_sync(0xffffffffu, z, o);
#pragma unroll
        for (int e = 0; e < NEXP; e++) pe[e] += __shfl_xor_sync(0xffffffffu, pe[e], o);
    }
    if (lane == 0) {
        float zl = (float)NEXP * (z / (float)((size_t)TOKENS * NEXP));
        float aux = 0.f;
#pragma unroll
        for (int e = 0; e < NEXP; e++) {
            float pm = pe[e] / (float)TOKENS;
            aux += pm * logf(pm + 1e-9f);
        }
        out[(size_t)TOKENS * HDIM    ] = zl;
        out[(size_t)TOKENS * HDIM + 1] = (float)NEXP * aux;
    }
}

// ---------------- launch ----------------
#define G1_SMEM ((2*G1_AS + 4*G1_BS) * 4)   // 73728 bytes
#define G2_SMEM ((2*G2_AS + 2*G2_BS) * 4)   // 71680 bytes

extern "C" void kernel_launch(void* const* d_in, const int* in_sizes, int n_in,
                              void* d_out, int out_size) {
    const float* x        = (const float*)d_in[0];
    const float* w_router = (const float*)d_in[1];
    const float* w_gate   = (const float*)d_in[2];
    const float* w_up     = (const float*)d_in[3];
    const float* w_down   = (const float*)d_in[4];
    float* out = (float*)d_out;

    cudaFuncSetAttribute(gemm1_kernel, cudaFuncAttributeMaxDynamicSharedMemorySize, G1_SMEM);
    cudaFuncSetAttribute(gemm2_kernel, cudaFuncAttributeMaxDynamicSharedMemorySize, G2_SMEM);

    zero_kernel<<<1, 32>>>();
    router_kernel<<<RBLOCKS, 256>>>(x, w_router);
    scan_kernel<<<1, 32>>>();
    scatter_kernel<<<TOKENS/256, 256>>>();
    gemm1_kernel<<<dim3(FFDIM/64, 64, NEXP), 256, G1_SMEM>>>(x, w_gate, w_up);
    gemm2_kernel<<<dim3(HDIM/128, 64, NEXP), 256, G2_SMEM>>>(w_down);
    combine_kernel<<<(TOKENS*256)/256, 256>>>(out);
    loss_kernel<<<1, 32>>>(out);
}